// round 16
// baseline (speedup 1.0000x reference)
#include <cuda_runtime.h>
#include <math.h>

#define NW 22

// FINAL (converged, held since R10; best total 8.64us x2, kernel 6.85-6.91us).
// Single-wave fused kernel: 128 blocks x 1024 threads, 8 float4 outputs/thread.
//
// Session conclusion (R2-R15, 11 distinct implementations, 6 reruns):
//  - Pinned at the chip's global-write BYTE wall (~2.4 TB/s for this 16 MB
//    stream). Invariant across STG.128/STG.256/TMA-bulk/hybrid stores, grid
//    shapes, cache policies, load batching, and schedules. STG.256 (half the
//    requests, same bytes) measured flat -> bytes-limited, not request-limited.
//  - Identical binaries measure 8.64-8.93us total (noise +-0.3us).
//  - Algorithmic win: 22-qubit RY+CNOT-ring overlap factorized into two
//    1024-entry product tables + one 32-entry pre-contracted matmul tail
//    (23.9us baseline -> 8.64us, 2.77x).
//
// Math (rel_err 3.5e-6):
//   out[4b+2i+j] = |TA[(b>>9)&1023] * TB[b&1023]| * S[c19,c0,c1,i,j]
//   c19=b&1, c0=(b>>19)&1, c1=(b>>18)&1
//   TA indexed by c_1..c_10 (bit t = c_{10-t}),  wires 2..10
//   TB indexed by c_10..c_19 (bit t = c_{19-t}), wires 11..19
//   b_w = c_{w-1}^c_w  ->  u = v ^ (v>>1)
//
// Per thread (b = (blk<<13)+(k<<10)+t):
//   B-index = b & 1023 = t                      -> k-invariant, load once
//   sS-index uses bits 0,18,19 of b             -> k-invariant, load once
//   A-index = (b>>9)&1023, warp-uniform         -> 1 broadcast LDS per k

__global__ void __launch_bounds__(1024) qk_fused(const float* __restrict__ x,
                                                 const float* __restrict__ y,
                                                 float4* __restrict__ out) {
    __shared__ float cx[NW], sx[NW], cy[NW], sy[NW];
    __shared__ float pc[NW], ps[NW];       // pair products cx*cy, sx*sy
    __shared__ float sTA[1024], sTB[1024];
    __shared__ float4 sS[8];               // [c19][c0][c1] -> (i,j) quad
    const int t = threadIdx.x;

    if (t < NW) {
        float sxx, cxx, syy, cyy;
        __sincosf(0.5f * x[t], &sxx, &cxx);
        __sincosf(0.5f * y[t], &syy, &cyy);
        cx[t] = cxx; sx[t] = sxx; cy[t] = cyy; sy[t] = syy;
        pc[t] = cxx * cyy; ps[t] = sxx * syy;
    }
    __syncthreads();

    // Each thread fills one entry of each table.
    {
        int u = t ^ (t >> 1);
        float a = 1.0f, bb = 1.0f;
        #pragma unroll
        for (int j = 0; j < 9; ++j) {
            bool bit = (u >> j) & 1;
            a  *= bit ? ps[10 - j] : pc[10 - j];   // wires 2..10
            bb *= bit ? ps[19 - j] : pc[19 - j];   // wires 11..19
        }
        sTA[t] = a;
        sTB[t] = bb;
    }

    // S table: pre-contracted 2x2 matmul tail + abs (32 scalars).
    if (t < 32) {
        int j   =  t        & 1;
        int i   = (t >> 1)  & 1;
        int c1  = (t >> 2)  & 1;
        int c0  = (t >> 3)  & 1;
        int c19 = (t >> 4)  & 1;
        float s = 0.0f;
        #pragma unroll
        for (int k = 0; k < 2; ++k) {
            float ty = ((c19 ^ i)     ? sy[20] : cy[20])
                     * ((i   ^ k)     ? sy[21] : cy[21])
                     * ((c0  ^ k)     ? sy[0]  : cy[0])
                     * ((c0 ^ c1 ^ k) ? sy[1]  : cy[1]);
            float tx = ((c19 ^ k)     ? sx[20] : cx[20])
                     * ((k   ^ j)     ? sx[21] : cx[21])
                     * ((c0  ^ j)     ? sx[0]  : cx[0])
                     * ((c0 ^ c1 ^ j) ? sx[1]  : cx[1]);
            s += ty * tx;
        }
        reinterpret_cast<float*>(sS)[t] = fabsf(s);
    }
    __syncthreads();

    // Main loop: 8 coalesced float4 stores per thread, interleaved LDS/STG.
    const unsigned base = (unsigned)blockIdx.x << 13;
    const float B = sTB[t];                                     // b&1023 == t
    const unsigned b0 = base + (unsigned)t;
    const float4 s = sS[((b0 & 1u) << 2) | (((b0 >> 19) & 1u) << 1)
                        | ((b0 >> 18) & 1u)];                   // k-invariant
    const float Bsx = B * s.x, Bsy = B * s.y, Bsz = B * s.z, Bsw = B * s.w;

    #pragma unroll
    for (int k = 0; k < 8; ++k) {
        unsigned b = b0 + ((unsigned)k << 10);
        float A = fabsf(sTA[(b >> 9) & 1023u]);                 // warp-uniform LDS
        float4 o;
        o.x = fabsf(A * Bsx);
        o.y = fabsf(A * Bsy);
        o.z = fabsf(A * Bsz);
        o.w = fabsf(A * Bsw);
        out[b] = o;
    }
}

extern "C" void kernel_launch(void* const* d_in, const int* in_sizes, int n_in,
                              void* d_out, int out_size) {
    const float* x = (const float*)d_in[0];
    const float* y = (const float*)d_in[1];
    // 2^20 float4 outputs / (1024 threads * 8 per thread) = 128 blocks
    qk_fused<<<128, 1024>>>(x, y, (float4*)d_out);
}

// round 17
// speedup vs baseline: 1.0295x; 1.0295x over previous
#include <cuda_runtime.h>
#include <math.h>

#define NW 22

// FINAL (converged, held since R10; best total 8.64us x2, kernel 6.85-6.91us).
// Single-wave fused kernel: 128 blocks x 1024 threads, 8 float4 outputs/thread.
//
// Session conclusion (R2-R16, 11 distinct implementations, 7 reruns):
//  - Pinned at the chip's global-write BYTE wall (~2.4 TB/s for this 16 MB
//    stream). Invariant across STG.128/STG.256/TMA-bulk/hybrid stores, grid
//    shapes, cache policies, load batching, and schedules. STG.256 (half the
//    requests, same bytes) measured flat -> bytes-limited, not request-limited.
//  - Identical binaries measure 8.64-8.93us total (noise +-0.3us).
//  - Algorithmic win: 22-qubit RY+CNOT-ring overlap factorized into two
//    1024-entry product tables + one 32-entry pre-contracted matmul tail
//    (23.9us baseline -> 8.64us, 2.77x).
//
// Math (rel_err 3.5e-6):
//   out[4b+2i+j] = |TA[(b>>9)&1023] * TB[b&1023]| * S[c19,c0,c1,i,j]
//   c19=b&1, c0=(b>>19)&1, c1=(b>>18)&1
//   TA indexed by c_1..c_10 (bit t = c_{10-t}),  wires 2..10
//   TB indexed by c_10..c_19 (bit t = c_{19-t}), wires 11..19
//   b_w = c_{w-1}^c_w  ->  u = v ^ (v>>1)
//
// Per thread (b = (blk<<13)+(k<<10)+t):
//   B-index = b & 1023 = t                      -> k-invariant, load once
//   sS-index uses bits 0,18,19 of b             -> k-invariant, load once
//   A-index = (b>>9)&1023, warp-uniform         -> 1 broadcast LDS per k

__global__ void __launch_bounds__(1024) qk_fused(const float* __restrict__ x,
                                                 const float* __restrict__ y,
                                                 float4* __restrict__ out) {
    __shared__ float cx[NW], sx[NW], cy[NW], sy[NW];
    __shared__ float pc[NW], ps[NW];       // pair products cx*cy, sx*sy
    __shared__ float sTA[1024], sTB[1024];
    __shared__ float4 sS[8];               // [c19][c0][c1] -> (i,j) quad
    const int t = threadIdx.x;

    if (t < NW) {
        float sxx, cxx, syy, cyy;
        __sincosf(0.5f * x[t], &sxx, &cxx);
        __sincosf(0.5f * y[t], &syy, &cyy);
        cx[t] = cxx; sx[t] = sxx; cy[t] = cyy; sy[t] = syy;
        pc[t] = cxx * cyy; ps[t] = sxx * syy;
    }
    __syncthreads();

    // Each thread fills one entry of each table.
    {
        int u = t ^ (t >> 1);
        float a = 1.0f, bb = 1.0f;
        #pragma unroll
        for (int j = 0; j < 9; ++j) {
            bool bit = (u >> j) & 1;
            a  *= bit ? ps[10 - j] : pc[10 - j];   // wires 2..10
            bb *= bit ? ps[19 - j] : pc[19 - j];   // wires 11..19
        }
        sTA[t] = a;
        sTB[t] = bb;
    }

    // S table: pre-contracted 2x2 matmul tail + abs (32 scalars).
    if (t < 32) {
        int j   =  t        & 1;
        int i   = (t >> 1)  & 1;
        int c1  = (t >> 2)  & 1;
        int c0  = (t >> 3)  & 1;
        int c19 = (t >> 4)  & 1;
        float s = 0.0f;
        #pragma unroll
        for (int k = 0; k < 2; ++k) {
            float ty = ((c19 ^ i)     ? sy[20] : cy[20])
                     * ((i   ^ k)     ? sy[21] : cy[21])
                     * ((c0  ^ k)     ? sy[0]  : cy[0])
                     * ((c0 ^ c1 ^ k) ? sy[1]  : cy[1]);
            float tx = ((c19 ^ k)     ? sx[20] : cx[20])
                     * ((k   ^ j)     ? sx[21] : cx[21])
                     * ((c0  ^ j)     ? sx[0]  : cx[0])
                     * ((c0 ^ c1 ^ j) ? sx[1]  : cx[1]);
            s += ty * tx;
        }
        reinterpret_cast<float*>(sS)[t] = fabsf(s);
    }
    __syncthreads();

    // Main loop: 8 coalesced float4 stores per thread, interleaved LDS/STG.
    const unsigned base = (unsigned)blockIdx.x << 13;
    const float B = sTB[t];                                     // b&1023 == t
    const unsigned b0 = base + (unsigned)t;
    const float4 s = sS[((b0 & 1u) << 2) | (((b0 >> 19) & 1u) << 1)
                        | ((b0 >> 18) & 1u)];                   // k-invariant
    const float Bsx = B * s.x, Bsy = B * s.y, Bsz = B * s.z, Bsw = B * s.w;

    #pragma unroll
    for (int k = 0; k < 8; ++k) {
        unsigned b = b0 + ((unsigned)k << 10);
        float A = fabsf(sTA[(b >> 9) & 1023u]);                 // warp-uniform LDS
        float4 o;
        o.x = fabsf(A * Bsx);
        o.y = fabsf(A * Bsy);
        o.z = fabsf(A * Bsz);
        o.w = fabsf(A * Bsw);
        out[b] = o;
    }
}

extern "C" void kernel_launch(void* const* d_in, const int* in_sizes, int n_in,
                              void* d_out, int out_size) {
    const float* x = (const float*)d_in[0];
    const float* y = (const float*)d_in[1];
    // 2^20 float4 outputs / (1024 threads * 8 per thread) = 128 blocks
    qk_fused<<<128, 1024>>>(x, y, (float4*)d_out);
}